// round 15
// baseline (speedup 1.0000x reference)
#include <cuda_runtime.h>
#include <cuda_fp16.h>

// ---- problem constants ----
#define Bb   32      // batch
#define Ii   32      // input capsules
#define AIN  16      // input atoms
#define OD   10      // output classes
#define OA   16      // output atoms
#define HWp  144     // 12*12 spatial
#define Kk   160     // OD*OA
#define NPOS (Bb*HWp)   // 4608 positions

// votes scratch in fp16, layout [pos][d][i][a]  (47.2 MB)
__device__ __half g_votesh[(size_t)NPOS * Ii * Kk];

// ============================================================================
// Kernel A: votes[b,i,d,a,hw] = sum_ain x[b,i,ain,hw] * w[i,ain,d*16+a]
// One block per (b,i). 160 threads, t = d*16+a. 8-position inner blocking.
// ============================================================================
__global__ void __launch_bounds__(160) votes_kernel(const float* __restrict__ x,
                                                    const float* __restrict__ w)
{
    const int bi = blockIdx.x;        // b*32 + i
    const int b  = bi >> 5;
    const int i  = bi & 31;
    const int t  = threadIdx.x;       // 0..159 == d*16+a

    __shared__ __align__(16) float xs[AIN * HWp];   // 9 KB

    // x tile load via float4: 2304 floats = 576 float4
    {
        const float4* xg4 = (const float4*)(x + (size_t)bi * (AIN * HWp));
        float4* xs4 = (float4*)xs;
        for (int idx = t; idx < (AIN * HWp) / 4; idx += 160) xs4[idx] = xg4[idx];
    }

    float wr[AIN];
#pragma unroll
    for (int ai = 0; ai < AIN; ai++)
        wr[ai] = w[(i * AIN + ai) * Kk + t];

    __syncthreads();

    __half* vbase = g_votesh + (size_t)(b * HWp) * (Ii * Kk)
                  + (size_t)((t >> 4) * (Ii * OA) + i * OA + (t & 15));

#pragma unroll 2
    for (int h8 = 0; h8 < HWp / 8; h8++) {          // 18 iterations
        float4 acc0 = make_float4(0.f, 0.f, 0.f, 0.f);
        float4 acc1 = make_float4(0.f, 0.f, 0.f, 0.f);
#pragma unroll
        for (int ai = 0; ai < AIN; ai++) {
            const float4 xv0 = *(const float4*)(xs + ai * HWp + h8 * 8);
            const float4 xv1 = *(const float4*)(xs + ai * HWp + h8 * 8 + 4);
            acc0.x = fmaf(wr[ai], xv0.x, acc0.x);
            acc0.y = fmaf(wr[ai], xv0.y, acc0.y);
            acc0.z = fmaf(wr[ai], xv0.z, acc0.z);
            acc0.w = fmaf(wr[ai], xv0.w, acc0.w);
            acc1.x = fmaf(wr[ai], xv1.x, acc1.x);
            acc1.y = fmaf(wr[ai], xv1.y, acc1.y);
            acc1.z = fmaf(wr[ai], xv1.z, acc1.z);
            acc1.w = fmaf(wr[ai], xv1.w, acc1.w);
        }
        __half* p = vbase + (size_t)(h8 * 8) * (Ii * Kk);
        p[0]               = __float2half_rn(acc0.x);
        p[Ii * Kk]         = __float2half_rn(acc0.y);
        p[2 * (Ii * Kk)]   = __float2half_rn(acc0.z);
        p[3 * (Ii * Kk)]   = __float2half_rn(acc0.w);
        p[4 * (Ii * Kk)]   = __float2half_rn(acc1.x);
        p[5 * (Ii * Kk)]   = __float2half_rn(acc1.y);
        p[6 * (Ii * Kk)]   = __float2half_rn(acc1.z);
        p[7 * (Ii * Kk)]   = __float2half_rn(acc1.w);
    }
}

// ============================================================================
// Kernel B: routing (R11 structure). One block per 2 positions, 10 warps
// (warp = class d), positions sequential.
// __launch_bounds__(320, 5): target <=40 regs -> 5 blocks/SM (72% occ).
// ============================================================================
__global__ void __launch_bounds__(320, 5) route_kernel(const float* __restrict__ bias,
                                                       float* __restrict__ out)
{
    const int pos0 = blockIdx.x * 2;        // pos0, pos0+1 share batch b
    const int d    = threadIdx.x >> 5;      // warp id = class
    const int lane = threadIdx.x & 31;
    const int i16  = lane & 15;             // capsule pair index
    const int grp  = lane >> 4;             // atom group

    __shared__ float2 ex2[2][OD][16];       // exp(logit) pairs per softmax round

    // ---- issue all 4 vote loads (2 capsules x 2 positions) up front ----
    const __half* vb = g_votesh + (size_t)pos0 * (Ii * Kk)
                     + d * (Ii * OA) + (i16 * 2) * OA + grp * 8;
    uint4 raw[4];
    raw[0] = *(const uint4*)(vb);                   // pos0, capsule 2*i16
    raw[1] = *(const uint4*)(vb + OA);              // pos0, capsule 2*i16+1
    raw[2] = *(const uint4*)(vb + Ii * Kk);         // pos1, capsule 2*i16
    raw[3] = *(const uint4*)(vb + Ii * Kk + OA);    // pos1, capsule 2*i16+1

    const int atom = grp * 8 + ((lane >> 1) & 7);   // atom this lane owns post-reduce
    const float bv = bias[d * OA + atom];
    const int b   = pos0 / HWp;
    const int hw0 = pos0 - b * HWp;
    const unsigned FULL = 0xffffffffu;

#pragma unroll
    for (int p = 0; p < 2; p++) {
        // ---- convert this position's votes to fp32 ----
        float va0[8], va1[8];
        {
            const __half2* h0 = (const __half2*)&raw[2 * p];
            const __half2* h1 = (const __half2*)&raw[2 * p + 1];
#pragma unroll
            for (int k = 0; k < 4; k++) {
                float2 f0 = __half22float2(h0[k]);
                float2 f1 = __half22float2(h1[k]);
                va0[2 * k] = f0.x; va0[2 * k + 1] = f0.y;
                va1[2 * k] = f1.x; va1[2 * k + 1] = f1.y;
            }
        }

        float logitA = 0.f, logitB = 0.f;
        float outP = 0.f, outScale = 0.f;

#pragma unroll
        for (int r = 0; r < 3; r++) {
            // ---- softmax over d ----
            float routeA, routeB;
            if (r == 0) {
                routeA = routeB = 0.1f;
            } else {
                float e0 = __expf(logitA), e1 = __expf(logitB);
                if (grp == 0) ex2[r - 1][d][i16] = make_float2(e0, e1);
                __syncthreads();
                float sA = 0.f, sB = 0.f;
#pragma unroll
                for (int d2 = 0; d2 < OD; d2++) {
                    float2 v = ex2[r - 1][d2][i16];
                    sA += v.x; sB += v.y;
                }
                routeA = __fdividef(e0, sA);
                routeB = __fdividef(e1, sB);
            }

            // ---- q[k] = routeA*va0[k] + routeB*va1[k] (8 own-group atoms) ----
            float q[8];
#pragma unroll
            for (int k = 0; k < 8; k++)
                q[k] = fmaf(routeB, va1[k], routeA * va0[k]);

            // ---- atom-splitting reduce over 16-lane half ----
            {
                const bool hi = (lane & 8) != 0;
#pragma unroll
                for (int k = 0; k < 4; k++) {
                    float snd = hi ? q[k] : q[k + 4];
                    float rcv = __shfl_xor_sync(FULL, snd, 8);
                    q[k] = (hi ? q[k + 4] : q[k]) + rcv;
                }
            }
            {
                const bool hi = (lane & 4) != 0;
#pragma unroll
                for (int k = 0; k < 2; k++) {
                    float snd = hi ? q[k] : q[k + 2];
                    float rcv = __shfl_xor_sync(FULL, snd, 4);
                    q[k] = (hi ? q[k + 2] : q[k]) + rcv;
                }
            }
            float s;
            {
                const bool hi = (lane & 2) != 0;
                float snd = hi ? q[0] : q[1];
                float rcv = __shfl_xor_sync(FULL, snd, 2);
                s = (hi ? q[1] : q[0]) + rcv;
            }
            s += __shfl_xor_sync(FULL, s, 1);

            const float P = s + bv;         // pre-squash preact for `atom`

            if (r < 2) {
                // ---- broadcast own-group pre-squash atoms ----
                float act[8];
#pragma unroll
                for (int k = 0; k < 8; k++)
                    act[k] = __shfl_sync(FULL, P, (lane & 16) | (k << 1));

                float n2p = 0.f;
#pragma unroll
                for (int k = 0; k < 8; k++) n2p = fmaf(act[k], act[k], n2p);
                float n2 = n2p + __shfl_xor_sync(FULL, n2p, 16);
                float scale = __fdividef(sqrtf(n2), 1.f + n2);

                float dA = 0.f, dB = 0.f;
#pragma unroll
                for (int k = 0; k < 8; k++) {
                    dA = fmaf(va0[k], act[k], dA);
                    dB = fmaf(va1[k], act[k], dB);
                }
                dA += __shfl_xor_sync(FULL, dA, 16);
                dB += __shfl_xor_sync(FULL, dB, 16);
                logitA = fmaf(dA, scale, logitA);
                logitB = fmaf(dB, scale, logitB);
            } else {
                float sq = P * P;
#pragma unroll
                for (int off = 16; off; off >>= 1)
                    sq += __shfl_xor_sync(FULL, sq, off);
                float n2 = 0.5f * sq;       // each atom counted twice
                outScale = __fdividef(sqrtf(n2), 1.f + n2);
                outP = P;
            }
        }

        // ---- output: even lane of each atom pair writes ----
        if ((lane & 1) == 0) {
            out[((size_t)(b * OD + d) * OA + atom) * HWp + hw0 + p] = outP * outScale;
        }
    }
}

extern "C" void kernel_launch(void* const* d_in, const int* in_sizes, int n_in,
                              void* d_out, int out_size)
{
    const float* x    = (const float*)d_in[0];   // [32,32,16,12,12]
    const float* w    = (const float*)d_in[1];   // [32,16,160]
    const float* bias = (const float*)d_in[2];   // [10,16,1,1]
    float* out = (float*)d_out;                  // [32,10,16,12,12]

    votes_kernel<<<Bb * Ii, 160>>>(x, w);
    route_kernel<<<NPOS / 2, 320>>>(bias, out);
}

// round 17
// speedup vs baseline: 1.3333x; 1.3333x over previous
#include <cuda_runtime.h>
#include <cuda_fp16.h>

// ---- problem constants ----
#define Bb   32      // batch
#define Ii   32      // input capsules
#define AIN  16      // input atoms
#define OD   10      // output classes
#define OA   16      // output atoms
#define HWp  144     // 12*12 spatial
#define Kk   160     // OD*OA
#define NPOS (Bb*HWp)   // 4608 positions

// votes scratch in fp16, layout [pos][d][i][a]  (47.2 MB)
__device__ __half g_votesh[(size_t)NPOS * Ii * Kk];

// ============================================================================
// Kernel A: votes[b,i,d,a,hw] = sum_ain x[b,i,ain,hw] * w[i,ain,d*16+a]
// One block per (b,i). 160 threads, t = d*16+a. fp16 math via __hfma2:
// half2 = (pos_even, pos_odd); 64 HFMA2 + 16 LDS.128 per 8-position iter.
// ============================================================================
__global__ void __launch_bounds__(160) votes_kernel(const float* __restrict__ x,
                                                    const float* __restrict__ w)
{
    const int bi = blockIdx.x;        // b*32 + i
    const int b  = bi >> 5;
    const int i  = bi & 31;
    const int t  = threadIdx.x;       // 0..159 == d*16+a

    // x tile as half2 (pairs of adjacent positions): [AIN][72], row = 288B (16B-aligned)
    __shared__ __align__(16) __half2 xs2[AIN * (HWp / 2)];   // 4.5 KB

    // load + convert x[b,i,:,:]: 1152 float2 -> half2
    {
        const float2* xg2 = (const float2*)(x + (size_t)bi * (AIN * HWp));
        for (int idx = t; idx < AIN * (HWp / 2); idx += 160) {
            const float2 v = xg2[idx];
            xs2[idx] = __floats2half2_rn(v.x, v.y);
        }
    }

    // weight column broadcast into both halves
    __half2 w2[AIN];
#pragma unroll
    for (int ai = 0; ai < AIN; ai++) {
        const float wv = w[(i * AIN + ai) * Kk + t];   // coalesced
        w2[ai] = __half2half2(__float2half_rn(wv));
    }

    __syncthreads();

    __half* vbase = g_votesh + (size_t)(b * HWp) * (Ii * Kk)
                  + (size_t)((t >> 4) * (Ii * OA) + i * OA + (t & 15));

#pragma unroll 2
    for (int h8 = 0; h8 < HWp / 8; h8++) {          // 18 iterations, 8 positions
        __half2 a0 = __float2half2_rn(0.f);
        __half2 a1 = __float2half2_rn(0.f);
        __half2 a2 = __float2half2_rn(0.f);
        __half2 a3 = __float2half2_rn(0.f);
#pragma unroll
        for (int ai = 0; ai < AIN; ai++) {
            // ONE LDS.128 delivers 8 positions (4 half2)
            const uint4 xv = *(const uint4*)(xs2 + ai * (HWp / 2) + h8 * 4);
            const __half2* hx = (const __half2*)&xv;
            a0 = __hfma2(w2[ai], hx[0], a0);
            a1 = __hfma2(w2[ai], hx[1], a1);
            a2 = __hfma2(w2[ai], hx[2], a2);
            a3 = __hfma2(w2[ai], hx[3], a3);
        }
        __half* p = vbase + (size_t)(h8 * 8) * (Ii * Kk);
        p[0]               = __low2half(a0);
        p[Ii * Kk]         = __high2half(a0);
        p[2 * (Ii * Kk)]   = __low2half(a1);
        p[3 * (Ii * Kk)]   = __high2half(a1);
        p[4 * (Ii * Kk)]   = __low2half(a2);
        p[5 * (Ii * Kk)]   = __high2half(a2);
        p[6 * (Ii * Kk)]   = __low2half(a3);
        p[7 * (Ii * Kk)]   = __high2half(a3);
    }
}

// ============================================================================
// Kernel B: routing — EXACT R11 (best measured: 34.5us, 48 regs, 57% occ).
// One block per 2 positions, 10 warps (warp = class d), positions sequential.
// ============================================================================
__global__ void __launch_bounds__(320, 4) route_kernel(const float* __restrict__ bias,
                                                       float* __restrict__ out)
{
    const int pos0 = blockIdx.x * 2;        // pos0, pos0+1 share batch b
    const int d    = threadIdx.x >> 5;      // warp id = class
    const int lane = threadIdx.x & 31;
    const int i16  = lane & 15;             // capsule pair index
    const int grp  = lane >> 4;             // atom group

    __shared__ float2 ex2[2][OD][16];       // exp(logit) pairs per softmax round

    // ---- issue all 4 vote loads (2 capsules x 2 positions) up front ----
    const __half* vb = g_votesh + (size_t)pos0 * (Ii * Kk)
                     + d * (Ii * OA) + (i16 * 2) * OA + grp * 8;
    uint4 raw[4];
    raw[0] = *(const uint4*)(vb);                   // pos0, capsule 2*i16
    raw[1] = *(const uint4*)(vb + OA);              // pos0, capsule 2*i16+1
    raw[2] = *(const uint4*)(vb + Ii * Kk);         // pos1, capsule 2*i16
    raw[3] = *(const uint4*)(vb + Ii * Kk + OA);    // pos1, capsule 2*i16+1

    const int atom = grp * 8 + ((lane >> 1) & 7);   // atom this lane owns post-reduce
    const float bv = bias[d * OA + atom];
    const int b   = pos0 / HWp;
    const int hw0 = pos0 - b * HWp;
    const unsigned FULL = 0xffffffffu;

#pragma unroll
    for (int p = 0; p < 2; p++) {
        // ---- convert this position's votes to fp32 ----
        float va0[8], va1[8];
        {
            const __half2* h0 = (const __half2*)&raw[2 * p];
            const __half2* h1 = (const __half2*)&raw[2 * p + 1];
#pragma unroll
            for (int k = 0; k < 4; k++) {
                float2 f0 = __half22float2(h0[k]);
                float2 f1 = __half22float2(h1[k]);
                va0[2 * k] = f0.x; va0[2 * k + 1] = f0.y;
                va1[2 * k] = f1.x; va1[2 * k + 1] = f1.y;
            }
        }

        float logitA = 0.f, logitB = 0.f;
        float outP = 0.f, outScale = 0.f;

#pragma unroll
        for (int r = 0; r < 3; r++) {
            // ---- softmax over d ----
            float routeA, routeB;
            if (r == 0) {
                routeA = routeB = 0.1f;
            } else {
                float e0 = __expf(logitA), e1 = __expf(logitB);
                if (grp == 0) ex2[r - 1][d][i16] = make_float2(e0, e1);
                __syncthreads();
                float sA = 0.f, sB = 0.f;
#pragma unroll
                for (int d2 = 0; d2 < OD; d2++) {
                    float2 v = ex2[r - 1][d2][i16];
                    sA += v.x; sB += v.y;
                }
                routeA = __fdividef(e0, sA);
                routeB = __fdividef(e1, sB);
            }

            // ---- q[k] = routeA*va0[k] + routeB*va1[k] (8 own-group atoms) ----
            float q[8];
#pragma unroll
            for (int k = 0; k < 8; k++)
                q[k] = fmaf(routeB, va1[k], routeA * va0[k]);

            // ---- atom-splitting reduce over 16-lane half ----
            {
                const bool hi = (lane & 8) != 0;
#pragma unroll
                for (int k = 0; k < 4; k++) {
                    float snd = hi ? q[k] : q[k + 4];
                    float rcv = __shfl_xor_sync(FULL, snd, 8);
                    q[k] = (hi ? q[k + 4] : q[k]) + rcv;
                }
            }
            {
                const bool hi = (lane & 4) != 0;
#pragma unroll
                for (int k = 0; k < 2; k++) {
                    float snd = hi ? q[k] : q[k + 2];
                    float rcv = __shfl_xor_sync(FULL, snd, 4);
                    q[k] = (hi ? q[k + 2] : q[k]) + rcv;
                }
            }
            float s;
            {
                const bool hi = (lane & 2) != 0;
                float snd = hi ? q[0] : q[1];
                float rcv = __shfl_xor_sync(FULL, snd, 2);
                s = (hi ? q[1] : q[0]) + rcv;
            }
            s += __shfl_xor_sync(FULL, s, 1);

            const float P = s + bv;         // pre-squash preact for `atom`

            if (r < 2) {
                // ---- broadcast own-group pre-squash atoms ----
                float act[8];
#pragma unroll
                for (int k = 0; k < 8; k++)
                    act[k] = __shfl_sync(FULL, P, (lane & 16) | (k << 1));

                float n2p = 0.f;
#pragma unroll
                for (int k = 0; k < 8; k++) n2p = fmaf(act[k], act[k], n2p);
                float n2 = n2p + __shfl_xor_sync(FULL, n2p, 16);
                float scale = __fdividef(sqrtf(n2), 1.f + n2);

                float dA = 0.f, dB = 0.f;
#pragma unroll
                for (int k = 0; k < 8; k++) {
                    dA = fmaf(va0[k], act[k], dA);
                    dB = fmaf(va1[k], act[k], dB);
                }
                dA += __shfl_xor_sync(FULL, dA, 16);
                dB += __shfl_xor_sync(FULL, dB, 16);
                logitA = fmaf(dA, scale, logitA);
                logitB = fmaf(dB, scale, logitB);
            } else {
                float sq = P * P;
#pragma unroll
                for (int off = 16; off; off >>= 1)
                    sq += __shfl_xor_sync(FULL, sq, off);
                float n2 = 0.5f * sq;       // each atom counted twice
                outScale = __fdividef(sqrtf(n2), 1.f + n2);
                outP = P;
            }
        }

        // ---- output: even lane of each atom pair writes ----
        if ((lane & 1) == 0) {
            out[((size_t)(b * OD + d) * OA + atom) * HWp + hw0 + p] = outP * outScale;
        }
    }
}

extern "C" void kernel_launch(void* const* d_in, const int* in_sizes, int n_in,
                              void* d_out, int out_size)
{
    const float* x    = (const float*)d_in[0];   // [32,32,16,12,12]
    const float* w    = (const float*)d_in[1];   // [32,16,160]
    const float* bias = (const float*)d_in[2];   // [10,16,1,1]
    float* out = (float*)d_out;                  // [32,10,16,12,12]

    votes_kernel<<<Bb * Ii, 160>>>(x, w);
    route_kernel<<<NPOS / 2, 320>>>(bias, out);
}